// round 9
// baseline (speedup 1.0000x reference)
#include <cuda_runtime.h>
#include <math.h>
#include <stdint.h>

// Problem constants
#define HDIM 768
#define DDIM 128
#define BATCH 64
#define SQ 128
#define SD 1024
#define NTOK_Q (BATCH * SQ)   // 8192
#define NJCHUNK 8             // SD / 128
#define NBLK_Q (NTOK_Q / 128) // 64
#define NBLK_D (BATCH * NJCHUNK) // 512

#define KC 32                 // K chunk (floats)
#define LDK 36                // ring row stride words (9x16B odd -> conflict-free)
#define NSTAGE 3
#define STAGE_BYTES (128 * LDK * 4)      // 18432
#define RING_OFF 1024
#define SMEM_BYTES (RING_OFF + 2 * NSTAGE * STAGE_BYTES)   // 111616

// fused-kernel sub-layout inside the ring area (all offsets from smem+RING_OFF)
#define LDD 132                           // d-tile row stride words (33x16B odd)
#define DTILE_BYTES (128 * LDD * 4)       // 67584
#define QS_OFF DTILE_BYTES                // q stages: 67584, 86016
#define RED_OFF (QS_OFF + 2 * STAGE_BYTES)  // 104448 (1KB reduction scratch)

// Scratch (device globals: allocation-free per harness rules)
__device__ float g_q_emb[NTOK_Q * DDIM];            // 4 MB
__device__ float g_pmax[BATCH * NJCHUNK * SQ];      // 256 KB
__device__ float g_w_rna[DDIM * HDIM];              // 384 KB (tf32-rounded W)

// ---------------------------------------------------------------------------
// helpers
// ---------------------------------------------------------------------------
__device__ __forceinline__ uint32_t s2u(const void* p) {
    return (uint32_t)__cvta_generic_to_shared(p);
}
__device__ __forceinline__ float f2tff(float x) {
    uint32_t u; asm("cvt.rna.tf32.f32 %0, %1;" : "=r"(u) : "f"(x));
    return __uint_as_float(u);
}
__device__ __forceinline__ void cp16(uint32_t smem, const void* g) {
    asm volatile("cp.async.cg.shared.global [%0], [%1], 16;" :: "r"(smem), "l"(g));
}
#define CP_COMMIT() asm volatile("cp.async.commit_group;" ::: "memory")
#define CP_WAIT(n)  asm volatile("cp.async.wait_group %0;" :: "n"(n) : "memory")

#define MBARRIER_INIT(mb, n) \
    asm volatile("mbarrier.init.shared.b64 [%0], %1;" :: "r"((uint32_t)(mb)), "r"((uint32_t)(n)) : "memory")
#define MBARRIER_ARRIVE(mb) \
    asm volatile("mbarrier.arrive.shared.b64 _, [%0];" :: "r"((uint32_t)(mb)) : "memory")

__device__ __forceinline__ void mbar_wait(uint32_t mb, uint32_t parity) {
    uint32_t done;
    asm volatile("{\n\t.reg .pred p;\n\t"
                 "mbarrier.try_wait.parity.acquire.cta.shared::cta.b64 p, [%1], %2;\n\t"
                 "selp.b32 %0, 1, 0, p;\n\t}" : "=r"(done) : "r"(mb), "r"(parity) : "memory");
    while (!done) {
        asm volatile("{\n\t.reg .pred p;\n\t"
                     "mbarrier.try_wait.parity.acquire.cta.shared::cta.b64 p, [%1], %2, 0x989680;\n\t"
                     "selp.b32 %0, 1, 0, p;\n\t}" : "=r"(done) : "r"(mb), "r"(parity) : "memory");
    }
}

__device__ __forceinline__ void ldsm4(uint32_t& r0, uint32_t& r1, uint32_t& r2,
                                      uint32_t& r3, uint32_t addr) {
    asm volatile("ldmatrix.sync.aligned.m8n8.x4.shared.b16 {%0,%1,%2,%3}, [%4];"
                 : "=r"(r0), "=r"(r1), "=r"(r2), "=r"(r3) : "r"(addr));
}
__device__ __forceinline__ void mma8(float c[4], const uint32_t a[4], const uint32_t b[2]) {
    asm volatile("mma.sync.aligned.m16n8k8.row.col.f32.tf32.tf32.f32 "
                 "{%0,%1,%2,%3}, {%4,%5,%6,%7}, {%8,%9}, {%0,%1,%2,%3};"
                 : "+f"(c[0]), "+f"(c[1]), "+f"(c[2]), "+f"(c[3])
                 : "r"(a[0]), "r"(a[1]), "r"(a[2]), "r"(a[3]),
                   "r"(b[0]), "r"(b[1]));
}

// barriers: projection full/empty s=0..2 at sb+8+s*16 (+8 = empty)
// q-phase full2/empty2 s=0..1 at sb+56+s*16 (+8 = empty2)
#define MB_FULL(sb, s)   ((sb) + 8 + (uint32_t)(s) * 16)
#define MB_EMPTY(sb, s)  ((sb) + 8 + (uint32_t)(s) * 16 + 8)
#define MB2_FULL(sb, s)  ((sb) + 56 + (uint32_t)(s) * 16)
#define MB2_EMPTY(sb, s) ((sb) + 56 + (uint32_t)(s) * 16 + 8)

// Consume one KC=32 ring stage (projection / q-side layout LDK).
__device__ __forceinline__ void consume_stage(uint32_t aB, uint32_t bB,
                                              const uint32_t aOff[2],
                                              const uint32_t bOff[4],
                                              float acc[2][8][4])
{
#pragma unroll
    for (int ks = 0; ks < 4; ks++) {
        const int k8 = ks * 8;
        uint32_t af[2][4], bf[8][2];
#pragma unroll
        for (int i = 0; i < 2; i++)
            ldsm4(af[i][0], af[i][1], af[i][2], af[i][3], aB + (aOff[i] + k8) * 4);
#pragma unroll
        for (int jj = 0; jj < 4; jj++) {
            uint32_t r0, r1, r2, r3;
            ldsm4(r0, r1, r2, r3, bB + (bOff[jj] + k8) * 4);
            bf[2 * jj][0] = r0;  bf[2 * jj][1] = r1;
            bf[2 * jj + 1][0] = r2;  bf[2 * jj + 1][1] = r3;
        }
#pragma unroll
        for (int i = 0; i < 2; i++)
#pragma unroll
            for (int j = 0; j < 8; j++) mma8(acc[i][j], af[i], bf[j]);
    }
}

__device__ __forceinline__ void frag_offsets(int warp, int lane,
                                             uint32_t aOff[2], uint32_t bOff[4],
                                             int& warpM, int& warpN)
{
    warpM = (warp & 3) * 32;
    warpN = (warp >> 2) * 64;
    const int l7 = lane & 7, b3 = (lane >> 3) & 1, b4 = (lane >> 4) & 1;
#pragma unroll
    for (int i = 0; i < 2; i++)
        aOff[i] = (uint32_t)((warpM + i * 16 + l7 + b3 * 8) * LDK + b4 * 4);
#pragma unroll
    for (int jj = 0; jj < 4; jj++)
        bOff[jj] = (uint32_t)((warpN + jj * 16 + b4 * 8 + l7) * LDK + b3 * 4);
}

// ---------------------------------------------------------------------------
// Kernel 0: tf32-round W once.
// ---------------------------------------------------------------------------
__global__ __launch_bounds__(256) void round_w(const float* __restrict__ W)
{
    int i = blockIdx.x * 256 + threadIdx.x;
    float4 v = ((const float4*)W)[i];
    v.x = f2tff(v.x); v.y = f2tff(v.y); v.z = f2tff(v.z); v.w = f2tff(v.w);
    ((float4*)g_w_rna)[i] = v;
}

// ---------------------------------------------------------------------------
// Kernel 1: QUERY projection + L2 normalize (warp-specialized, R8-proven).
// Writes g_q_emb tf32-rounded.
// ---------------------------------------------------------------------------
__global__ __launch_bounds__(320, 2) void proj_q(
    const float* __restrict__ Xq, const int* __restrict__ Mq,
    float* __restrict__ Eq)
{
    extern __shared__ char smem[];
    const uint32_t sbase = s2u(smem);
    const int tid  = threadIdx.x;
    const int lane = tid & 31;
    const int warp = tid >> 5;
    const int row0 = blockIdx.x * 128;
    const float* gA = Xq + (size_t)row0 * HDIM;
    const float* gB = g_w_rna;

    if (tid == 0) {
#pragma unroll
        for (int s = 0; s < NSTAGE; s++) {
            MBARRIER_INIT(MB_FULL(sbase, s), 64);
            MBARRIER_INIT(MB_EMPTY(sbase, s), 256);
        }
    }
    __syncthreads();
    const int NC = HDIM / KC;   // 24

    if (warp >= 8) {
        const int ptid = tid - 256;
        int st = 0, ph = 1;
        for (int m = 0; m < NC; m++) {
            mbar_wait(MB_EMPTY(sbase, st), (uint32_t)ph);
            const float* a = gA + m * KC;
            const float* b = gB + m * KC;
            const uint32_t smA = sbase + RING_OFF + (uint32_t)st * STAGE_BYTES;
            const uint32_t smB = smA + NSTAGE * STAGE_BYTES;
#pragma unroll
            for (int i = 0; i < 16; i++) {
                int idx = ptid + i * 64;
                int r = idx >> 3;
                int kq = (idx & 7) * 4;
                uint32_t off = (uint32_t)(r * LDK + kq) * 4;
                cp16(smA + off, a + (size_t)r * HDIM + kq);
                cp16(smB + off, b + (size_t)r * HDIM + kq);
            }
            CP_COMMIT();
            if (m >= 2) { CP_WAIT(2); MBARRIER_ARRIVE(MB_FULL(sbase, (m - 2) % NSTAGE)); }
            if (++st == NSTAGE) { st = 0; ph ^= 1; }
        }
        CP_WAIT(1); MBARRIER_ARRIVE(MB_FULL(sbase, (NC - 2) % NSTAGE));
        CP_WAIT(0); MBARRIER_ARRIVE(MB_FULL(sbase, (NC - 1) % NSTAGE));
        return;
    }

    uint32_t aOff[2], bOff[4];
    int warpM, warpN;
    frag_offsets(warp, lane, aOff, bOff, warpM, warpN);
    const int wn = warp >> 2;
    const int g = lane >> 2, tig = lane & 3;

    float acc[2][8][4];
#pragma unroll
    for (int i = 0; i < 2; i++)
#pragma unroll
        for (int j = 0; j < 8; j++)
#pragma unroll
            for (int e = 0; e < 4; e++) acc[i][j][e] = 0.f;

    {
        int st = 0, ph = 0;
        for (int k = 0; k < NC; k++) {
            mbar_wait(MB_FULL(sbase, st), (uint32_t)ph);
            const uint32_t aB = sbase + RING_OFF + (uint32_t)st * STAGE_BYTES;
            consume_stage(aB, aB + NSTAGE * STAGE_BYTES, aOff, bOff, acc);
            MBARRIER_ARRIVE(MB_EMPTY(sbase, st));
            if (++st == NSTAGE) { st = 0; ph ^= 1; }
        }
    }
    asm volatile("bar.sync 1, 256;" ::: "memory");

    float* ssb = (float*)(smem + RING_OFF);
#pragma unroll
    for (int i = 0; i < 2; i++) {
        float sl = 0.f, sh = 0.f;
#pragma unroll
        for (int j = 0; j < 8; j++) {
            sl += acc[i][j][0] * acc[i][j][0] + acc[i][j][1] * acc[i][j][1];
            sh += acc[i][j][2] * acc[i][j][2] + acc[i][j][3] * acc[i][j][3];
        }
        sl += __shfl_xor_sync(0xffffffffu, sl, 1);
        sl += __shfl_xor_sync(0xffffffffu, sl, 2);
        sh += __shfl_xor_sync(0xffffffffu, sh, 1);
        sh += __shfl_xor_sync(0xffffffffu, sh, 2);
        if (tig == 0) {
            ssb[wn * 128 + warpM + i * 16 + g]     = sl;
            ssb[wn * 128 + warpM + i * 16 + 8 + g] = sh;
        }
    }
    asm volatile("bar.sync 1, 256;" ::: "memory");
#pragma unroll
    for (int i = 0; i < 2; i++) {
        const int rl = warpM + i * 16 + g;
        const int rh = rl + 8;
        const float scl = (float)Mq[row0 + rl] / fmaxf(sqrtf(ssb[rl] + ssb[128 + rl]), 1e-12f);
        const float sch = (float)Mq[row0 + rh] / fmaxf(sqrtf(ssb[rh] + ssb[128 + rh]), 1e-12f);
#pragma unroll
        for (int j = 0; j < 8; j++) {
            float2 v;
            v.x = f2tff(acc[i][j][0] * scl); v.y = f2tff(acc[i][j][1] * scl);
            *(float2*)&Eq[(size_t)(row0 + rl) * DDIM + warpN + j * 8 + tig * 2] = v;
            v.x = f2tff(acc[i][j][2] * sch); v.y = f2tff(acc[i][j][3] * sch);
            *(float2*)&Eq[(size_t)(row0 + rh) * DDIM + warpN + j * 8 + tig * 2] = v;
        }
    }
}

// ---------------------------------------------------------------------------
// Kernel 2: FUSED doc projection + normalize + maxsim partial-max.
// Block t (0..511): doc tokens [t*128, t*128+128), batch b = t/8.
// Phase 1: warp-specialized projection (as proj_q) -> acc.
// Phase 2: normalize; store tf32 doc tile to smem (stride LDD).
// Phase 3: producers stream q_emb[b] in 4 K-chunks (2-stage mbarrier ring);
//          consumers MMA q x d^T and reduce row-max -> g_pmax.  No Ed store.
// ---------------------------------------------------------------------------
__global__ __launch_bounds__(320, 2) void fused_d(
    const float* __restrict__ Xd, const int* __restrict__ Md)
{
    extern __shared__ char smem[];
    const uint32_t sbase = s2u(smem);
    const uint32_t ring  = sbase + RING_OFF;
    const int tid  = threadIdx.x;
    const int lane = tid & 31;
    const int warp = tid >> 5;
    const int row0 = blockIdx.x * 128;          // doc token base
    const int b    = blockIdx.x >> 3;           // batch
    const float* gA = Xd + (size_t)row0 * HDIM;
    const float* gB = g_w_rna;
    const float* qe = g_q_emb + (size_t)b * SQ * DDIM;

    if (tid == 0) {
#pragma unroll
        for (int s = 0; s < NSTAGE; s++) {
            MBARRIER_INIT(MB_FULL(sbase, s), 64);
            MBARRIER_INIT(MB_EMPTY(sbase, s), 256);
        }
#pragma unroll
        for (int s = 0; s < 2; s++) {
            MBARRIER_INIT(MB2_FULL(sbase, s), 64);
            MBARRIER_INIT(MB2_EMPTY(sbase, s), 256);
        }
    }
    __syncthreads();
    const int NC = HDIM / KC;   // 24

    if (warp >= 8) {
        // ---------------- PRODUCER ----------------
        const int ptid = tid - 256;
        {
            int st = 0, ph = 1;
            for (int m = 0; m < NC; m++) {
                mbar_wait(MB_EMPTY(sbase, st), (uint32_t)ph);
                const float* a = gA + m * KC;
                const float* w = gB + m * KC;
                const uint32_t smA = ring + (uint32_t)st * STAGE_BYTES;
                const uint32_t smB = smA + NSTAGE * STAGE_BYTES;
#pragma unroll
                for (int i = 0; i < 16; i++) {
                    int idx = ptid + i * 64;
                    int r = idx >> 3;
                    int kq = (idx & 7) * 4;
                    uint32_t off = (uint32_t)(r * LDK + kq) * 4;
                    cp16(smA + off, a + (size_t)r * HDIM + kq);
                    cp16(smB + off, w + (size_t)r * HDIM + kq);
                }
                CP_COMMIT();
                if (m >= 2) { CP_WAIT(2); MBARRIER_ARRIVE(MB_FULL(sbase, (m - 2) % NSTAGE)); }
                if (++st == NSTAGE) { st = 0; ph ^= 1; }
            }
            CP_WAIT(1); MBARRIER_ARRIVE(MB_FULL(sbase, (NC - 2) % NSTAGE));
            CP_WAIT(0); MBARRIER_ARRIVE(MB_FULL(sbase, (NC - 1) % NSTAGE));
        }
        __syncthreads();   // #1: projection ring fully consumed; q area free

        // q phase: 4 chunks of 32 dims, 2-stage ring
        auto load_q = [&](int m) {
            const float* src = qe + m * KC;
            const uint32_t dst = ring + QS_OFF + (uint32_t)(m & 1) * STAGE_BYTES;
#pragma unroll
            for (int i = 0; i < 16; i++) {
                int idx = ptid + i * 64;
                int r = idx >> 3;
                int kq = (idx & 7) * 4;
                cp16(dst + (uint32_t)(r * LDK + kq) * 4, src + (size_t)r * DDIM + kq);
            }
            CP_COMMIT();
        };
        load_q(0);
        load_q(1);
        CP_WAIT(1); MBARRIER_ARRIVE(MB2_FULL(sbase, 0));
        mbar_wait(MB2_EMPTY(sbase, 0), 0);     // consumers done with chunk 0
        load_q(2);
        CP_WAIT(1); MBARRIER_ARRIVE(MB2_FULL(sbase, 1));
        mbar_wait(MB2_EMPTY(sbase, 1), 0);     // consumers done with chunk 1
        load_q(3);
        CP_WAIT(1); MBARRIER_ARRIVE(MB2_FULL(sbase, 0));   // chunk 2 (phase 1)
        CP_WAIT(0); MBARRIER_ARRIVE(MB2_FULL(sbase, 1));   // chunk 3 (phase 1)
        return;
    }

    // ---------------- CONSUMER ----------------
    uint32_t aOff[2], bOff[4];
    int warpM, warpN;
    frag_offsets(warp, lane, aOff, bOff, warpM, warpN);
    const int wn = warp >> 2;
    const int g = lane >> 2, tig = lane & 3;
    const int l7 = lane & 7, b3 = (lane >> 3) & 1, b4 = (lane >> 4) & 1;

    float acc[2][8][4];
#pragma unroll
    for (int i = 0; i < 2; i++)
#pragma unroll
        for (int j = 0; j < 8; j++)
#pragma unroll
            for (int e = 0; e < 4; e++) acc[i][j][e] = 0.f;

    {
        int st = 0, ph = 0;
        for (int k = 0; k < NC; k++) {
            mbar_wait(MB_FULL(sbase, st), (uint32_t)ph);
            const uint32_t aB = ring + (uint32_t)st * STAGE_BYTES;
            consume_stage(aB, aB + NSTAGE * STAGE_BYTES, aOff, bOff, acc);
            MBARRIER_ARRIVE(MB_EMPTY(sbase, st));
            if (++st == NSTAGE) { st = 0; ph ^= 1; }
        }
    }
    __syncthreads();   // #1 (with producers)

    // normalize: sums via quad shuffle + cross-warp smem at RED_OFF
    float* ssb = (float*)(smem + RING_OFF + RED_OFF);
#pragma unroll
    for (int i = 0; i < 2; i++) {
        float sl = 0.f, sh = 0.f;
#pragma unroll
        for (int j = 0; j < 8; j++) {
            sl += acc[i][j][0] * acc[i][j][0] + acc[i][j][1] * acc[i][j][1];
            sh += acc[i][j][2] * acc[i][j][2] + acc[i][j][3] * acc[i][j][3];
        }
        sl += __shfl_xor_sync(0xffffffffu, sl, 1);
        sl += __shfl_xor_sync(0xffffffffu, sl, 2);
        sh += __shfl_xor_sync(0xffffffffu, sh, 1);
        sh += __shfl_xor_sync(0xffffffffu, sh, 2);
        if (tig == 0) {
            ssb[wn * 128 + warpM + i * 16 + g]     = sl;
            ssb[wn * 128 + warpM + i * 16 + 8 + g] = sh;
        }
    }
    asm volatile("bar.sync 1, 256;" ::: "memory");

    // store normalized tf32 doc tile to smem (rows = doc tokens, stride LDD)
    float* dtile = (float*)(smem + RING_OFF);
#pragma unroll
    for (int i = 0; i < 2; i++) {
        const int rl = warpM + i * 16 + g;
        const int rh = rl + 8;
        const float scl = (float)Md[row0 + rl] / fmaxf(sqrtf(ssb[rl] + ssb[128 + rl]), 1e-12f);
        const float sch = (float)Md[row0 + rh] / fmaxf(sqrtf(ssb[rh] + ssb[128 + rh]), 1e-12f);
#pragma unroll
        for (int j = 0; j < 8; j++) {
            const int col = warpN + j * 8 + tig * 2;
            float2 v;
            v.x = f2tff(acc[i][j][0] * scl); v.y = f2tff(acc[i][j][1] * scl);
            *(float2*)&dtile[rl * LDD + col] = v;
            v.x = f2tff(acc[i][j][2] * sch); v.y = f2tff(acc[i][j][3] * sch);
            *(float2*)&dtile[rh * LDD + col] = v;
        }
    }
    asm volatile("bar.sync 1, 256;" ::: "memory");   // d tile visible

    // maxsim: sim = q (A, M=128 q-tokens) x d^T (B, N=128 docs), K=128 dims
    uint32_t bOffD[4];
#pragma unroll
    for (int jj = 0; jj < 4; jj++)
        bOffD[jj] = (uint32_t)((warpN + jj * 16 + b4 * 8 + l7) * LDD + b3 * 4);

#pragma unroll
    for (int i = 0; i < 2; i++)
#pragma unroll
        for (int j = 0; j < 8; j++)
#pragma unroll
            for (int e = 0; e < 4; e++) acc[i][j][e] = 0.f;

    {
        int st2 = 0, ph2 = 0;
        for (int m = 0; m < 4; m++) {
            mbar_wait(MB2_FULL(sbase, st2), (uint32_t)ph2);
            const uint32_t qB = ring + QS_OFF + (uint32_t)st2 * STAGE_BYTES;
#pragma unroll
            for (int ks = 0; ks < 4; ks++) {
                const int k8 = ks * 8;
                uint32_t af[2][4], bf[8][2];
#pragma unroll
                for (int i = 0; i < 2; i++)
                    ldsm4(af[i][0], af[i][1], af[i][2], af[i][3], qB + (aOff[i] + k8) * 4);
#pragma unroll
                for (int jj = 0; jj < 4; jj++) {
                    uint32_t r0, r1, r2, r3;
                    ldsm4(r0, r1, r2, r3, ring + (bOffD[jj] + m * KC + k8) * 4);
                    bf[2 * jj][0] = r0;  bf[2 * jj][1] = r1;
                    bf[2 * jj + 1][0] = r2;  bf[2 * jj + 1][1] = r3;
                }
#pragma unroll
                for (int i = 0; i < 2; i++)
#pragma unroll
                    for (int j = 0; j < 8; j++) mma8(acc[i][j], af[i], bf[j]);
            }
            MBARRIER_ARRIVE(MB2_EMPTY(sbase, st2));
            if (++st2 == 2) { st2 = 0; ph2 ^= 1; }
        }
    }

    // row max over the 128 docs of this tile -> g_pmax[blockIdx.x*SQ + row]
    float* mxb = (float*)(smem + RING_OFF + RED_OFF);
#pragma unroll
    for (int i = 0; i < 2; i++) {
        float ml = acc[i][0][0], mh = acc[i][0][2];
#pragma unroll
        for (int j = 0; j < 8; j++) {
            ml = fmaxf(ml, fmaxf(acc[i][j][0], acc[i][j][1]));
            mh = fmaxf(mh, fmaxf(acc[i][j][2], acc[i][j][3]));
        }
        ml = fmaxf(ml, __shfl_xor_sync(0xffffffffu, ml, 1));
        ml = fmaxf(ml, __shfl_xor_sync(0xffffffffu, ml, 2));
        mh = fmaxf(mh, __shfl_xor_sync(0xffffffffu, mh, 1));
        mh = fmaxf(mh, __shfl_xor_sync(0xffffffffu, mh, 2));
        if (tig == 0) {
            mxb[wn * 128 + warpM + i * 16 + g]     = ml;
            mxb[wn * 128 + warpM + i * 16 + 8 + g] = mh;
        }
    }
    asm volatile("bar.sync 1, 256;" ::: "memory");
    if (tid < 128)
        g_pmax[(size_t)blockIdx.x * SQ + tid] = fmaxf(mxb[tid], mxb[128 + tid]);
}

// ---------------------------------------------------------------------------
// Kernel 3: finalize. out[b] = sum_i max_jc pmax[b, jc, i]
// ---------------------------------------------------------------------------
__global__ __launch_bounds__(128) void finalize_kernel(float* __restrict__ out)
{
    const int b = blockIdx.x;
    const int i = threadIdx.x;
    float m = g_pmax[((size_t)b * NJCHUNK + 0) * SQ + i];
#pragma unroll
    for (int jc = 1; jc < NJCHUNK; jc++)
        m = fmaxf(m, g_pmax[((size_t)b * NJCHUNK + jc) * SQ + i]);
#pragma unroll
    for (int o = 16; o > 0; o >>= 1)
        m += __shfl_xor_sync(0xffffffffu, m, o, 32);
    __shared__ float s[4];
    if ((i & 31) == 0) s[i >> 5] = m;
    __syncthreads();
    if (i == 0) out[b] = s[0] + s[1] + s[2] + s[3];
}

// ---------------------------------------------------------------------------
extern "C" void kernel_launch(void* const* d_in, const int* in_sizes, int n_in,
                              void* d_out, int out_size)
{
    const float* qh = (const float*)d_in[0];   // [64,128,768]
    const int*   qm = (const int*)  d_in[1];   // [64,128]
    const float* dh = (const float*)d_in[2];   // [64,1024,768]
    const int*   dm = (const int*)  d_in[3];   // [64,1024]
    const float* W  = (const float*)d_in[4];   // [128,768]
    float* out = (float*)d_out;                // [64]

    float* gq = nullptr;
    cudaGetSymbolAddress((void**)&gq, g_q_emb);

    cudaFuncSetAttribute(proj_q,  cudaFuncAttributeMaxDynamicSharedMemorySize, SMEM_BYTES);
    cudaFuncSetAttribute(fused_d, cudaFuncAttributeMaxDynamicSharedMemorySize, SMEM_BYTES);

    round_w<<<(DDIM * HDIM / 4) / 256, 256>>>(W);
    proj_q<<<NBLK_Q, 320, SMEM_BYTES>>>(qh, qm, gq);
    fused_d<<<NBLK_D, 320, SMEM_BYTES>>>(dh, dm);
    finalize_kernel<<<BATCH, 128>>>(out);
}

// round 10
// speedup vs baseline: 1.4650x; 1.4650x over previous
#include <cuda_runtime.h>
#include <cuda_fp16.h>
#include <math.h>
#include <stdint.h>

// Problem constants
#define HDIM 768
#define DDIM 128
#define BATCH 64
#define SQ 128
#define SD 1024
#define NTOK_Q (BATCH * SQ)   // 8192
#define NTOK_D (BATCH * SD)   // 65536
#define NJCHUNK 8             // SD / 128
#define NBLK_Q (NTOK_Q / 128) // 64
#define NBLK_D (NTOK_D / 128) // 512

#define KC 32                 // K chunk (elements)
#define NSTAGE 3
#define LDH 40                // fp16 stage row stride (units): 80B = 5x16B odd
#define HSTG (128 * LDH * 2)  // 10240 B per fp16 stage
#define RAWLD 36              // raw fp32 row stride (floats): 144B = 9x16B odd
#define RAWSTG (128 * RAWLD * 4)   // 18432 B
#define RING_OFF 1024
// proj layout (relative to ring = smem + RING_OFF):
//   Aring 3*HSTG @0, Bring 3*HSTG @30720, raw 2*RAWSTG @61440, RED @98304
#define BRING_OFF (3 * HSTG)       // 30720
#define RAW_OFF   (6 * HSTG)       // 61440
#define PROJ_RED  (RAW_OFF + 2 * RAWSTG)   // 98304
#define PROJ_SMEM (RING_OFF + PROJ_RED + 2048)   // 101376
// maxsim layout: Aring 3 @0, Bring 3 @30720, RED @61440
#define MS_RED   (6 * HSTG)
#define MS_SMEM  (RING_OFF + MS_RED + 2048)      // 64512

// Scratch (device globals: allocation-free per harness rules)
__device__ __half g_q_emb[NTOK_Q * DDIM];            // 2 MB
__device__ __half g_d_emb[(size_t)NTOK_D * DDIM];    // 16 MB
__device__ float  g_pmax[BATCH * NJCHUNK * SQ];      // 256 KB
__device__ __half g_w_h[DDIM * HDIM];                // 192 KB (fp16 W)

// ---------------------------------------------------------------------------
// helpers
// ---------------------------------------------------------------------------
__device__ __forceinline__ uint32_t s2u(const void* p) {
    return (uint32_t)__cvta_generic_to_shared(p);
}
__device__ __forceinline__ void cp16(uint32_t smem, const void* g) {
    asm volatile("cp.async.cg.shared.global [%0], [%1], 16;" :: "r"(smem), "l"(g));
}
#define CP_COMMIT() asm volatile("cp.async.commit_group;" ::: "memory")
#define CP_WAIT(n)  asm volatile("cp.async.wait_group %0;" :: "n"(n) : "memory")

#define MBARRIER_INIT(mb, n) \
    asm volatile("mbarrier.init.shared.b64 [%0], %1;" :: "r"((uint32_t)(mb)), "r"((uint32_t)(n)) : "memory")
#define MBARRIER_ARRIVE(mb) \
    asm volatile("mbarrier.arrive.shared.b64 _, [%0];" :: "r"((uint32_t)(mb)) : "memory")

__device__ __forceinline__ void mbar_wait(uint32_t mb, uint32_t parity) {
    uint32_t done;
    asm volatile("{\n\t.reg .pred p;\n\t"
                 "mbarrier.try_wait.parity.acquire.cta.shared::cta.b64 p, [%1], %2;\n\t"
                 "selp.b32 %0, 1, 0, p;\n\t}" : "=r"(done) : "r"(mb), "r"(parity) : "memory");
    while (!done) {
        asm volatile("{\n\t.reg .pred p;\n\t"
                     "mbarrier.try_wait.parity.acquire.cta.shared::cta.b64 p, [%1], %2, 0x989680;\n\t"
                     "selp.b32 %0, 1, 0, p;\n\t}" : "=r"(done) : "r"(mb), "r"(parity) : "memory");
    }
}

__device__ __forceinline__ void ldsm4(uint32_t& r0, uint32_t& r1, uint32_t& r2,
                                      uint32_t& r3, uint32_t addr) {
    asm volatile("ldmatrix.sync.aligned.m8n8.x4.shared.b16 {%0,%1,%2,%3}, [%4];"
                 : "=r"(r0), "=r"(r1), "=r"(r2), "=r"(r3) : "r"(addr));
}
__device__ __forceinline__ void mma16(float c[4], const uint32_t a[4], const uint32_t b[2]) {
    asm volatile("mma.sync.aligned.m16n8k16.row.col.f32.f16.f16.f32 "
                 "{%0,%1,%2,%3}, {%4,%5,%6,%7}, {%8,%9}, {%0,%1,%2,%3};"
                 : "+f"(c[0]), "+f"(c[1]), "+f"(c[2]), "+f"(c[3])
                 : "r"(a[0]), "r"(a[1]), "r"(a[2]), "r"(a[3]),
                   "r"(b[0]), "r"(b[1]));
}

// barriers: full[s] at sb+8+s*16, empty[s] at +8
#define MB_FULL(sb, s)  ((sb) + 8 + (uint32_t)(s) * 16)
#define MB_EMPTY(sb, s) ((sb) + 8 + (uint32_t)(s) * 16 + 8)

// fp16 fragment offsets (units of __half), [rows][k] storage, stride LDH.
__device__ __forceinline__ void frag_offsets16(int warp, int lane,
                                               uint32_t aOff[2], uint32_t bOff[4],
                                               int& warpM, int& warpN)
{
    warpM = (warp & 3) * 32;
    warpN = (warp >> 2) * 64;
    const int l7 = lane & 7, b3 = (lane >> 3) & 1, b4 = (lane >> 4) & 1;
#pragma unroll
    for (int i = 0; i < 2; i++)
        aOff[i] = (uint32_t)((warpM + i * 16 + l7 + b3 * 8) * LDH + b4 * 8);
#pragma unroll
    for (int jj = 0; jj < 4; jj++)
        bOff[jj] = (uint32_t)((warpN + jj * 16 + b4 * 8 + l7) * LDH + b3 * 8);
}

// Consume one KC=32 fp16 stage: 2 k16 steps, each 6 ldsm.x4 + 16 mma per warp.
__device__ __forceinline__ void consume_stage16(uint32_t aB, uint32_t bB,
                                                const uint32_t aOff[2],
                                                const uint32_t bOff[4],
                                                float acc[2][8][4])
{
#pragma unroll
    for (int ks = 0; ks < 2; ks++) {
        const uint32_t kb = ks * 32;   // 16 fp16 = 32 bytes
        uint32_t af[2][4], bf[8][2];
#pragma unroll
        for (int i = 0; i < 2; i++)
            ldsm4(af[i][0], af[i][1], af[i][2], af[i][3], aB + aOff[i] * 2 + kb);
#pragma unroll
        for (int jj = 0; jj < 4; jj++) {
            uint32_t r0, r1, r2, r3;
            ldsm4(r0, r1, r2, r3, bB + bOff[jj] * 2 + kb);
            bf[2 * jj][0] = r0;  bf[2 * jj][1] = r1;
            bf[2 * jj + 1][0] = r2;  bf[2 * jj + 1][1] = r3;
        }
#pragma unroll
        for (int i = 0; i < 2; i++)
#pragma unroll
            for (int j = 0; j < 8; j++) mma16(acc[i][j], af[i], bf[j]);
    }
}

// ---------------------------------------------------------------------------
// Kernel 0: convert W fp32 -> fp16 once (operand exactly representable).
// ---------------------------------------------------------------------------
__global__ __launch_bounds__(256) void cvt_w(const float* __restrict__ W)
{
    int i = blockIdx.x * 256 + threadIdx.x;      // float4 index
    float4 v = ((const float4*)W)[i];
    __half2 h0 = __floats2half2_rn(v.x, v.y);
    __half2 h1 = __floats2half2_rn(v.z, v.w);
    uint2 u;
    u.x = *(uint32_t*)&h0;  u.y = *(uint32_t*)&h1;
    *(uint2*)&g_w_h[(size_t)i * 4] = u;
}

// ---------------------------------------------------------------------------
// Kernel 1: projection + L2 normalize, fp16 tensor path, warp-specialized.
// 320 threads: warps 0-7 consumers (4m x 2n, 128x128 tile, KC=32, 3-stage),
// warps 8-9 producers: cp.async X fp32 -> raw staging, cvt -> fp16 A ring;
// cp.async W fp16 -> B ring directly. Unified grid (q blocks then d blocks).
// Embeddings written fp16 (maxsim operands exactly representable).
// ---------------------------------------------------------------------------
__global__ __launch_bounds__(320, 2) void proj_tc(
    const float* __restrict__ Xq, const int* __restrict__ Mq,
    const float* __restrict__ Xd, const int* __restrict__ Md)
{
    extern __shared__ char smem[];
    const uint32_t sbase = s2u(smem);
    const uint32_t ring  = sbase + RING_OFF;
    const int tid  = threadIdx.x;
    const int lane = tid & 31;
    const int warp = tid >> 5;

    const bool isQ = blockIdx.x < NBLK_Q;
    const int  rb  = isQ ? blockIdx.x : (blockIdx.x - NBLK_Q);
    const int  row0 = rb * 128;
    const float* X = isQ ? Xq : Xd;
    const int*   M = isQ ? Mq : Md;
    __half*      E = isQ ? g_q_emb : (g_d_emb + (size_t)row0 * DDIM - (size_t)row0 * DDIM);
    E = isQ ? g_q_emb : g_d_emb;
    const float* gA = X + (size_t)row0 * HDIM;

    if (tid == 0) {
#pragma unroll
        for (int s = 0; s < NSTAGE; s++) {
            MBARRIER_INIT(MB_FULL(sbase, s), 64);
            MBARRIER_INIT(MB_EMPTY(sbase, s), 256);
        }
    }
    __syncthreads();
    const int NC = HDIM / KC;   // 24

    if (warp >= 8) {
        // ---------------- PRODUCER (warps 8,9; 64 threads) ----------------
        const int ptid = tid - 256;

        // cvt one chunk: raw[(mm)&1] fp32 -> Aring[mm%3] fp16
        auto cvt_store = [&](int mm) {
            const int buf = mm & 1;
            const int stp = mm % NSTAGE;
#pragma unroll
            for (int h = 0; h < 2; h++) {
                const int row = ptid + h * 64;
                const char* rbase = smem + RING_OFF + RAW_OFF + buf * RAWSTG + row * (RAWLD * 4);
                char* abase = smem + RING_OFF + stp * HSTG + row * (LDH * 2);
#pragma unroll
                for (int j2 = 0; j2 < 4; j2++) {
                    float4 f0 = *(const float4*)(rbase + j2 * 32);
                    float4 f1 = *(const float4*)(rbase + j2 * 32 + 16);
                    __half2 h0 = __floats2half2_rn(f0.x, f0.y);
                    __half2 h1 = __floats2half2_rn(f0.z, f0.w);
                    __half2 h2 = __floats2half2_rn(f1.x, f1.y);
                    __half2 h3 = __floats2half2_rn(f1.z, f1.w);
                    uint4 u;
                    u.x = *(uint32_t*)&h0;  u.y = *(uint32_t*)&h1;
                    u.z = *(uint32_t*)&h2;  u.w = *(uint32_t*)&h3;
                    *(uint4*)(abase + j2 * 16) = u;
                }
            }
        };

        int ph = 1;
        for (int m = 0; m < NC; m++) {
            const int st = m % NSTAGE;
            mbar_wait(MB_EMPTY(sbase, st), (uint32_t)ph);
            // X fp32 chunk m -> raw[m&1]
            const float* a = gA + m * KC;
            const uint32_t rawdst = ring + RAW_OFF + (uint32_t)(m & 1) * RAWSTG;
#pragma unroll
            for (int i = 0; i < 16; i++) {
                int idx = ptid + i * 64;
                int r = idx >> 3, c = (idx & 7) * 4;
                cp16(rawdst + (uint32_t)(r * RAWLD + c) * 4, a + (size_t)r * HDIM + c);
            }
            // W fp16 chunk m -> Bring[st]
            const __half* w = g_w_h + m * KC;
            const uint32_t bdst = ring + BRING_OFF + (uint32_t)st * HSTG;
#pragma unroll
            for (int i = 0; i < 8; i++) {
                int idx = ptid + i * 64;
                int r = idx >> 2, c8 = (idx & 3) * 8;
                cp16(bdst + (uint32_t)(r * LDH + c8) * 2, w + (size_t)r * HDIM + c8);
            }
            CP_COMMIT();
            if (m >= 1) {
                CP_WAIT(1);
                asm volatile("bar.sync 2, 64;" ::: "memory");   // all producers' groups retired
                cvt_store(m - 1);
                MBARRIER_ARRIVE(MB_FULL(sbase, (m - 1) % NSTAGE));
            }
            if (st == NSTAGE - 1) ph ^= 1;
        }
        CP_WAIT(0);
        asm volatile("bar.sync 2, 64;" ::: "memory");
        cvt_store(NC - 1);
        MBARRIER_ARRIVE(MB_FULL(sbase, (NC - 1) % NSTAGE));
        return;
    }

    // ---------------- CONSUMER (warps 0-7; 256 threads) ----------------
    uint32_t aOff[2], bOff[4];
    int warpM, warpN;
    frag_offsets16(warp, lane, aOff, bOff, warpM, warpN);
    const int wn = warp >> 2;
    const int g = lane >> 2, tig = lane & 3;

    float acc[2][8][4];
#pragma unroll
    for (int i = 0; i < 2; i++)
#pragma unroll
        for (int j = 0; j < 8; j++)
#pragma unroll
            for (int e = 0; e < 4; e++) acc[i][j][e] = 0.f;

    {
        int st = 0, ph = 0;
        for (int k = 0; k < NC; k++) {
            mbar_wait(MB_FULL(sbase, st), (uint32_t)ph);
            consume_stage16(ring + (uint32_t)st * HSTG,
                            ring + BRING_OFF + (uint32_t)st * HSTG,
                            aOff, bOff, acc);
            MBARRIER_ARRIVE(MB_EMPTY(sbase, st));
            if (++st == NSTAGE) { st = 0; ph ^= 1; }
        }
    }
    asm volatile("bar.sync 1, 256;" ::: "memory");

    // ---- fused L2 normalize (mask folded into scale) ----
    float* ssb = (float*)(smem + RING_OFF + PROJ_RED);   // [2][128]
#pragma unroll
    for (int i = 0; i < 2; i++) {
        float sl = 0.f, sh = 0.f;
#pragma unroll
        for (int j = 0; j < 8; j++) {
            sl += acc[i][j][0] * acc[i][j][0] + acc[i][j][1] * acc[i][j][1];
            sh += acc[i][j][2] * acc[i][j][2] + acc[i][j][3] * acc[i][j][3];
        }
        sl += __shfl_xor_sync(0xffffffffu, sl, 1);
        sl += __shfl_xor_sync(0xffffffffu, sl, 2);
        sh += __shfl_xor_sync(0xffffffffu, sh, 1);
        sh += __shfl_xor_sync(0xffffffffu, sh, 2);
        if (tig == 0) {
            ssb[wn * 128 + warpM + i * 16 + g]     = sl;
            ssb[wn * 128 + warpM + i * 16 + 8 + g] = sh;
        }
    }
    asm volatile("bar.sync 1, 256;" ::: "memory");
#pragma unroll
    for (int i = 0; i < 2; i++) {
        const int rl = warpM + i * 16 + g;
        const int rh = rl + 8;
        const float scl = (float)M[row0 + rl] / fmaxf(sqrtf(ssb[rl] + ssb[128 + rl]), 1e-12f);
        const float sch = (float)M[row0 + rh] / fmaxf(sqrtf(ssb[rh] + ssb[128 + rh]), 1e-12f);
#pragma unroll
        for (int j = 0; j < 8; j++) {
            const int col = warpN + j * 8 + tig * 2;
            __half2 v;
            v = __floats2half2_rn(acc[i][j][0] * scl, acc[i][j][1] * scl);
            *(__half2*)&E[(size_t)(row0 + rl) * DDIM + col] = v;
            v = __floats2half2_rn(acc[i][j][2] * sch, acc[i][j][3] * sch);
            *(__half2*)&E[(size_t)(row0 + rh) * DDIM + col] = v;
        }
    }
}

// ---------------------------------------------------------------------------
// Kernel 2: per-batch similarity + partial max (fp16, 3-stage cp.async ring).
// Block (b, jc): [128 q x 128 docs], K = 128 dims (4 chunks of 32).
// ---------------------------------------------------------------------------
__global__ __launch_bounds__(256, 2) void maxsim_tc()
{
    extern __shared__ char smem[];
    const uint32_t sbase = s2u(smem);
    const uint32_t ring  = sbase + RING_OFF;
    const int tid  = threadIdx.x;
    const int lane = tid & 31;
    const int warp = tid >> 5;
    const int b  = blockIdx.x;
    const int jc = blockIdx.y;

    const __half* q = g_q_emb + (size_t)b * SQ * DDIM;
    const __half* d = g_d_emb + ((size_t)b * SD + (size_t)jc * 128) * DDIM;

    uint32_t aOff[2], bOff[4];
    int warpM, warpN;
    frag_offsets16(warp, lane, aOff, bOff, warpM, warpN);
    const int wn = warp >> 2;
    const int g = lane >> 2, tig = lane & 3;

    float acc[2][8][4];
#pragma unroll
    for (int i = 0; i < 2; i++)
#pragma unroll
        for (int j = 0; j < 8; j++)
#pragma unroll
            for (int e = 0; e < 4; e++) acc[i][j][e] = 0.f;

    auto load_stage = [&](int st, int m) {
        const __half* a  = q + m * KC;
        const __half* dd = d + m * KC;
        const uint32_t smA = ring + (uint32_t)st * HSTG;
        const uint32_t smB = ring + BRING_OFF + (uint32_t)st * HSTG;
#pragma unroll
        for (int i = 0; i < 2; i++) {
            int idx = tid + i * 256;         // [0,512)
            int r = idx >> 2, c8 = (idx & 3) * 8;
            uint32_t off = (uint32_t)(r * LDH + c8) * 2;
            cp16(smA + off, a + (size_t)r * DDIM + c8);
            cp16(smB + off, dd + (size_t)r * DDIM + c8);
        }
    };

    load_stage(0, 0); CP_COMMIT();
    load_stage(1, 1); CP_COMMIT();

    const int NC = DDIM / KC;   // 4
    int st = 0, stn = 2;
    for (int k = 0; k < NC; k++) {
        CP_WAIT(1);
        __syncthreads();
        const int m = k + 2;
        if (m < NC) { load_stage(stn, m); CP_COMMIT(); }
        consume_stage16(ring + (uint32_t)st * HSTG,
                        ring + BRING_OFF + (uint32_t)st * HSTG,
                        aOff, bOff, acc);
        st = (st + 1 == NSTAGE) ? 0 : st + 1;
        stn = (stn + 1 == NSTAGE) ? 0 : stn + 1;
    }
    __syncthreads();

    // ---- row max over this 128-doc chunk ----
    float* mxb = (float*)(smem + RING_OFF + MS_RED);   // [2][128]
#pragma unroll
    for (int i = 0; i < 2; i++) {
        float ml = acc[i][0][0], mh = acc[i][0][2];
#pragma unroll
        for (int j = 0; j < 8; j++) {
            ml = fmaxf(ml, fmaxf(acc[i][j][0], acc[i][j][1]));
            mh = fmaxf(mh, fmaxf(acc[i][j][2], acc[i][j][3]));
        }
        ml = fmaxf(ml, __shfl_xor_sync(0xffffffffu, ml, 1));
        ml = fmaxf(ml, __shfl_xor_sync(0xffffffffu, ml, 2));
        mh = fmaxf(mh, __shfl_xor_sync(0xffffffffu, mh, 1));
        mh = fmaxf(mh, __shfl_xor_sync(0xffffffffu, mh, 2));
        if (tig == 0) {
            mxb[wn * 128 + warpM + i * 16 + g]     = ml;
            mxb[wn * 128 + warpM + i * 16 + 8 + g] = mh;
        }
    }
    __syncthreads();
    if (tid < 128)
        g_pmax[((size_t)b * NJCHUNK + jc) * SQ + tid] =
            fmaxf(mxb[tid], mxb[128 + tid]);
}

// ---------------------------------------------------------------------------
// Kernel 3: finalize. out[b] = sum_i max_jc pmax[b, jc, i]
// ---------------------------------------------------------------------------
__global__ __launch_bounds__(128) void finalize_kernel(float* __restrict__ out)
{
    const int b = blockIdx.x;
    const int i = threadIdx.x;
    float m = g_pmax[((size_t)b * NJCHUNK + 0) * SQ + i];
#pragma unroll
    for (int jc = 1; jc < NJCHUNK; jc++)
        m = fmaxf(m, g_pmax[((size_t)b * NJCHUNK + jc) * SQ + i]);
#pragma unroll
    for (int o = 16; o > 0; o >>= 1)
        m += __shfl_xor_sync(0xffffffffu, m, o, 32);
    __shared__ float s[4];
    if ((i & 31) == 0) s[i >> 5] = m;
    __syncthreads();
    if (i == 0) out[b] = s[0] + s[1] + s[2] + s[3];
}

// ---------------------------------------------------------------------------
extern "C" void kernel_launch(void* const* d_in, const int* in_sizes, int n_in,
                              void* d_out, int out_size)
{
    const float* qh = (const float*)d_in[0];   // [64,128,768]
    const int*   qm = (const int*)  d_in[1];   // [64,128]
    const float* dh = (const float*)d_in[2];   // [64,1024,768]
    const int*   dm = (const int*)  d_in[3];   // [64,1024]
    const float* W  = (const float*)d_in[4];   // [128,768]
    float* out = (float*)d_out;                // [64]

    cudaFuncSetAttribute(proj_tc,   cudaFuncAttributeMaxDynamicSharedMemorySize, PROJ_SMEM);
    cudaFuncSetAttribute(maxsim_tc, cudaFuncAttributeMaxDynamicSharedMemorySize, MS_SMEM);

    cvt_w<<<(DDIM * HDIM / 4) / 256, 256>>>(W);
    proj_tc<<<NBLK_Q + NBLK_D, 320, PROJ_SMEM>>>(qh, qm, dh, dm);
    maxsim_tc<<<dim3(BATCH, NJCHUNK), 256, MS_SMEM>>>();
    finalize_kernel<<<BATCH, 128>>>(out);
}

// round 11
// speedup vs baseline: 1.5028x; 1.0258x over previous
#include <cuda_runtime.h>
#include <cuda_fp16.h>
#include <math.h>
#include <stdint.h>

// Problem constants
#define HDIM 768
#define DDIM 128
#define BATCH 64
#define SQ 128
#define SD 1024
#define NTOK_Q (BATCH * SQ)   // 8192
#define NTOK_D (BATCH * SD)   // 65536
#define NJCHUNK 8             // SD / 128
#define NBLK_Q (NTOK_Q / 128) // 64
#define NBLK_D (NTOK_D / 128) // 512

#define KC 32                 // K chunk (elements)
#define NSTAGE 3
#define LDH 40                // fp16 stage row stride (units): 80B = 5x16B odd
#define HSTG (128 * LDH * 2)  // 10240 B per fp16 stage
#define RAWLD 36              // raw fp32 row stride (floats): 144B = 9x16B odd
#define RAWSTG (128 * RAWLD * 4)   // 18432 B
#define RING_OFF 1024

// proj layout (relative to ring = smem + RING_OFF):
//   raw X ring 3*RAWSTG @0, W ring 3*HSTG @55296, Abuf 2*HSTG @86016, RED @106496
#define PBRING_OFF (3 * RAWSTG)            // 55296
#define ABUF_OFF  (PBRING_OFF + 3 * HSTG)  // 86016
#define PROJ_RED  (ABUF_OFF + 2 * HSTG)    // 106496
#define PROJ_SMEM (RING_OFF + PROJ_RED + 2048)   // 109568

// maxsim layout: Aring 3 @0, Bring 3 @30720, RED @61440
#define MS_BOFF  (3 * HSTG)
#define MS_RED   (6 * HSTG)
#define MS_SMEM  (RING_OFF + MS_RED + 2048)      // 64512

// Scratch (device globals: allocation-free per harness rules)
__device__ __half g_q_emb[NTOK_Q * DDIM];            // 2 MB
__device__ __half g_d_emb[(size_t)NTOK_D * DDIM];    // 16 MB
__device__ float  g_pmax[BATCH * NJCHUNK * SQ];      // 256 KB
__device__ __half g_w_h[DDIM * HDIM];                // 192 KB (fp16 W)

// ---------------------------------------------------------------------------
// helpers
// ---------------------------------------------------------------------------
__device__ __forceinline__ uint32_t s2u(const void* p) {
    return (uint32_t)__cvta_generic_to_shared(p);
}
__device__ __forceinline__ void cp16(uint32_t smem, const void* g) {
    asm volatile("cp.async.cg.shared.global [%0], [%1], 16;" :: "r"(smem), "l"(g));
}
#define CP_COMMIT() asm volatile("cp.async.commit_group;" ::: "memory")
#define CP_WAIT(n)  asm volatile("cp.async.wait_group %0;" :: "n"(n) : "memory")

#define MBARRIER_INIT(mb, n) \
    asm volatile("mbarrier.init.shared.b64 [%0], %1;" :: "r"((uint32_t)(mb)), "r"((uint32_t)(n)) : "memory")
#define MBARRIER_ARRIVE(mb) \
    asm volatile("mbarrier.arrive.shared.b64 _, [%0];" :: "r"((uint32_t)(mb)) : "memory")

__device__ __forceinline__ void mbar_wait(uint32_t mb, uint32_t parity) {
    uint32_t done;
    asm volatile("{\n\t.reg .pred p;\n\t"
                 "mbarrier.try_wait.parity.acquire.cta.shared::cta.b64 p, [%1], %2;\n\t"
                 "selp.b32 %0, 1, 0, p;\n\t}" : "=r"(done) : "r"(mb), "r"(parity) : "memory");
    while (!done) {
        asm volatile("{\n\t.reg .pred p;\n\t"
                     "mbarrier.try_wait.parity.acquire.cta.shared::cta.b64 p, [%1], %2, 0x989680;\n\t"
                     "selp.b32 %0, 1, 0, p;\n\t}" : "=r"(done) : "r"(mb), "r"(parity) : "memory");
    }
}

__device__ __forceinline__ void ldsm4(uint32_t& r0, uint32_t& r1, uint32_t& r2,
                                      uint32_t& r3, uint32_t addr) {
    asm volatile("ldmatrix.sync.aligned.m8n8.x4.shared.b16 {%0,%1,%2,%3}, [%4];"
                 : "=r"(r0), "=r"(r1), "=r"(r2), "=r"(r3) : "r"(addr));
}
__device__ __forceinline__ void mma16(float c[4], const uint32_t a[4], const uint32_t b[2]) {
    asm volatile("mma.sync.aligned.m16n8k16.row.col.f32.f16.f16.f32 "
                 "{%0,%1,%2,%3}, {%4,%5,%6,%7}, {%8,%9}, {%0,%1,%2,%3};"
                 : "+f"(c[0]), "+f"(c[1]), "+f"(c[2]), "+f"(c[3])
                 : "r"(a[0]), "r"(a[1]), "r"(a[2]), "r"(a[3]),
                   "r"(b[0]), "r"(b[1]));
}

// barriers: full[s] at sb+8+s*16, empty[s] at +8
#define MB_FULL(sb, s)  ((sb) + 8 + (uint32_t)(s) * 16)
#define MB_EMPTY(sb, s) ((sb) + 8 + (uint32_t)(s) * 16 + 8)

// fp16 fragment offsets (units of __half), [rows][k] storage, stride LDH.
__device__ __forceinline__ void frag_offsets16(int warp, int lane,
                                               uint32_t aOff[2], uint32_t bOff[4],
                                               int& warpM, int& warpN)
{
    warpM = (warp & 3) * 32;
    warpN = (warp >> 2) * 64;
    const int l7 = lane & 7, b3 = (lane >> 3) & 1, b4 = (lane >> 4) & 1;
#pragma unroll
    for (int i = 0; i < 2; i++)
        aOff[i] = (uint32_t)((warpM + i * 16 + l7 + b3 * 8) * LDH + b4 * 8);
#pragma unroll
    for (int jj = 0; jj < 4; jj++)
        bOff[jj] = (uint32_t)((warpN + jj * 16 + b4 * 8 + l7) * LDH + b3 * 8);
}

// Consume one KC=32 fp16 stage: 2 k16 steps, each 6 ldsm.x4 + 16 mma per warp.
__device__ __forceinline__ void consume_stage16(uint32_t aB, uint32_t bB,
                                                const uint32_t aOff[2],
                                                const uint32_t bOff[4],
                                                float acc[2][8][4])
{
#pragma unroll
    for (int ks = 0; ks < 2; ks++) {
        const uint32_t kb = ks * 32;   // 16 fp16 = 32 bytes
        uint32_t af[2][4], bf[8][2];
#pragma unroll
        for (int i = 0; i < 2; i++)
            ldsm4(af[i][0], af[i][1], af[i][2], af[i][3], aB + aOff[i] * 2 + kb);
#pragma unroll
        for (int jj = 0; jj < 4; jj++) {
            uint32_t r0, r1, r2, r3;
            ldsm4(r0, r1, r2, r3, bB + bOff[jj] * 2 + kb);
            bf[2 * jj][0] = r0;  bf[2 * jj][1] = r1;
            bf[2 * jj + 1][0] = r2;  bf[2 * jj + 1][1] = r3;
        }
#pragma unroll
        for (int i = 0; i < 2; i++)
#pragma unroll
            for (int j = 0; j < 8; j++) mma16(acc[i][j], af[i], bf[j]);
    }
}

// ---------------------------------------------------------------------------
// Kernel 0: convert W fp32 -> fp16 once (operand exactly representable).
// ---------------------------------------------------------------------------
__global__ __launch_bounds__(256) void cvt_w(const float* __restrict__ W)
{
    int i = blockIdx.x * 256 + threadIdx.x;      // float4 index
    float4 v = ((const float4*)W)[i];
    __half2 h0 = __floats2half2_rn(v.x, v.y);
    __half2 h1 = __floats2half2_rn(v.z, v.w);
    uint2 u;
    u.x = *(uint32_t*)&h0;  u.y = *(uint32_t*)&h1;
    *(uint2*)&g_w_h[(size_t)i * 4] = u;
}

// ---------------------------------------------------------------------------
// Kernel 1: projection + L2 normalize, fp16, warp-specialized.
// 320 threads: warps 8-9 = pure cp.async producers (X fp32 -> raw ring,
// W fp16 -> B ring, 3-stage).  Warps 0-7 = consumers: distributed fp32->fp16
// convert (raw -> double-buffered Abuf, 1 named barrier), ldmatrix + MMA.
// Unified grid (q blocks then d blocks). Embeddings written fp16.
// ---------------------------------------------------------------------------
__global__ __launch_bounds__(320, 2) void proj_tc(
    const float* __restrict__ Xq, const int* __restrict__ Mq,
    const float* __restrict__ Xd, const int* __restrict__ Md)
{
    extern __shared__ char smem[];
    const uint32_t sbase = s2u(smem);
    const uint32_t ring  = sbase + RING_OFF;
    const int tid  = threadIdx.x;
    const int lane = tid & 31;
    const int warp = tid >> 5;

    const bool isQ = blockIdx.x < NBLK_Q;
    const int  rb  = isQ ? blockIdx.x : (blockIdx.x - NBLK_Q);
    const int  row0 = rb * 128;
    const float* X = isQ ? Xq : Xd;
    const int*   M = isQ ? Mq : Md;
    __half*      E = isQ ? g_q_emb : g_d_emb;
    const float* gA = X + (size_t)row0 * HDIM;

    if (tid == 0) {
#pragma unroll
        for (int s = 0; s < NSTAGE; s++) {
            MBARRIER_INIT(MB_FULL(sbase, s), 64);
            MBARRIER_INIT(MB_EMPTY(sbase, s), 256);
        }
    }
    __syncthreads();
    const int NC = HDIM / KC;   // 24

    if (warp >= 8) {
        // ------------- PRODUCER (warps 8,9): cp.async only -------------
        const int ptid = tid - 256;
        int ph = 1;
        for (int m = 0; m < NC; m++) {
            const int st = m % NSTAGE;
            mbar_wait(MB_EMPTY(sbase, st), (uint32_t)ph);
            // X fp32 chunk m -> raw[st]
            const float* a = gA + m * KC;
            const uint32_t rawdst = ring + (uint32_t)st * RAWSTG;
#pragma unroll
            for (int i = 0; i < 16; i++) {
                int idx = ptid + i * 64;
                int r = idx >> 3, c = (idx & 7) * 4;
                cp16(rawdst + (uint32_t)(r * RAWLD + c) * 4, a + (size_t)r * HDIM + c);
            }
            // W fp16 chunk m -> Bring[st]
            const __half* w = g_w_h + m * KC;
            const uint32_t bdst = ring + PBRING_OFF + (uint32_t)st * HSTG;
#pragma unroll
            for (int i = 0; i < 8; i++) {
                int idx = ptid + i * 64;
                int r = idx >> 2, c8 = (idx & 3) * 8;
                cp16(bdst + (uint32_t)(r * LDH + c8) * 2, w + (size_t)r * HDIM + c8);
            }
            CP_COMMIT();
            if (m >= 2) { CP_WAIT(2); MBARRIER_ARRIVE(MB_FULL(sbase, (m - 2) % NSTAGE)); }
            if (st == NSTAGE - 1) ph ^= 1;
        }
        CP_WAIT(1); MBARRIER_ARRIVE(MB_FULL(sbase, (NC - 2) % NSTAGE));
        CP_WAIT(0); MBARRIER_ARRIVE(MB_FULL(sbase, (NC - 1) % NSTAGE));
        return;
    }

    // ------------- CONSUMER (warps 0-7; 256 threads) -------------
    uint32_t aOff[2], bOff[4];
    int warpM, warpN;
    frag_offsets16(warp, lane, aOff, bOff, warpM, warpN);
    const int wn = warp >> 2;
    const int g = lane >> 2, tig = lane & 3;

    float acc[2][8][4];
#pragma unroll
    for (int i = 0; i < 2; i++)
#pragma unroll
        for (int j = 0; j < 8; j++)
#pragma unroll
            for (int e = 0; e < 4; e++) acc[i][j][e] = 0.f;

    {
        int st = 0, ph = 0;
        for (int k = 0; k < NC; k++) {
            mbar_wait(MB_FULL(sbase, st), (uint32_t)ph);
            // distributed cvt: raw[st] fp32 -> Abuf[k&1] fp16
            // thread handles pairs p = tid, tid+256 of 512 (r = p&127, cp = p>>7)
            const char* rawb = smem + RING_OFF + (size_t)st * RAWSTG;
            char* ab = smem + RING_OFF + ABUF_OFF + (size_t)(k & 1) * HSTG;
#pragma unroll
            for (int i = 0; i < 2; i++) {
                int p = tid + i * 256;
                int r = p & 127, cp = p >> 7;
                const char* src = rawb + r * (RAWLD * 4) + cp * 32;
                float4 f0 = *(const float4*)(src);
                float4 f1 = *(const float4*)(src + 16);
                __half2 h0 = __floats2half2_rn(f0.x, f0.y);
                __half2 h1 = __floats2half2_rn(f0.z, f0.w);
                __half2 h2 = __floats2half2_rn(f1.x, f1.y);
                __half2 h3 = __floats2half2_rn(f1.z, f1.w);
                uint4 u;
                u.x = *(uint32_t*)&h0;  u.y = *(uint32_t*)&h1;
                u.z = *(uint32_t*)&h2;  u.w = *(uint32_t*)&h3;
                *(uint4*)(ab + r * (LDH * 2) + cp * 16) = u;
            }
            asm volatile("bar.sync 1, 256;" ::: "memory");   // Abuf visible
            consume_stage16(ring + ABUF_OFF + (uint32_t)(k & 1) * HSTG,
                            ring + PBRING_OFF + (uint32_t)st * HSTG,
                            aOff, bOff, acc);
            MBARRIER_ARRIVE(MB_EMPTY(sbase, st));
            if (++st == NSTAGE) { st = 0; ph ^= 1; }
        }
    }
    asm volatile("bar.sync 1, 256;" ::: "memory");

    // ---- fused L2 normalize (mask folded into scale) ----
    float* ssb = (float*)(smem + RING_OFF + PROJ_RED);   // [2][128]
#pragma unroll
    for (int i = 0; i < 2; i++) {
        float sl = 0.f, sh = 0.f;
#pragma unroll
        for (int j = 0; j < 8; j++) {
            sl += acc[i][j][0] * acc[i][j][0] + acc[i][j][1] * acc[i][j][1];
            sh += acc[i][j][2] * acc[i][j][2] + acc[i][j][3] * acc[i][j][3];
        }
        sl += __shfl_xor_sync(0xffffffffu, sl, 1);
        sl += __shfl_xor_sync(0xffffffffu, sl, 2);
        sh += __shfl_xor_sync(0xffffffffu, sh, 1);
        sh += __shfl_xor_sync(0xffffffffu, sh, 2);
        if (tig == 0) {
            ssb[wn * 128 + warpM + i * 16 + g]     = sl;
            ssb[wn * 128 + warpM + i * 16 + 8 + g] = sh;
        }
    }
    asm volatile("bar.sync 1, 256;" ::: "memory");
#pragma unroll
    for (int i = 0; i < 2; i++) {
        const int rl = warpM + i * 16 + g;
        const int rh = rl + 8;
        const float scl = (float)M[row0 + rl] / fmaxf(sqrtf(ssb[rl] + ssb[128 + rl]), 1e-12f);
        const float sch = (float)M[row0 + rh] / fmaxf(sqrtf(ssb[rh] + ssb[128 + rh]), 1e-12f);
#pragma unroll
        for (int j = 0; j < 8; j++) {
            const int col = warpN + j * 8 + tig * 2;
            __half2 v;
            v = __floats2half2_rn(acc[i][j][0] * scl, acc[i][j][1] * scl);
            *(__half2*)&E[(size_t)(row0 + rl) * DDIM + col] = v;
            v = __floats2half2_rn(acc[i][j][2] * sch, acc[i][j][3] * sch);
            *(__half2*)&E[(size_t)(row0 + rh) * DDIM + col] = v;
        }
    }
}

// ---------------------------------------------------------------------------
// Kernel 2: per-batch similarity + partial max (fp16, 3-stage cp.async ring).
// Block (b, jc): [128 q x 128 docs], K = 128 dims (4 chunks of 32).
// ---------------------------------------------------------------------------
__global__ __launch_bounds__(256, 2) void maxsim_tc()
{
    extern __shared__ char smem[];
    const uint32_t sbase = s2u(smem);
    const uint32_t ring  = sbase + RING_OFF;
    const int tid  = threadIdx.x;
    const int lane = tid & 31;
    const int warp = tid >> 5;
    const int b  = blockIdx.x;
    const int jc = blockIdx.y;

    const __half* q = g_q_emb + (size_t)b * SQ * DDIM;
    const __half* d = g_d_emb + ((size_t)b * SD + (size_t)jc * 128) * DDIM;

    uint32_t aOff[2], bOff[4];
    int warpM, warpN;
    frag_offsets16(warp, lane, aOff, bOff, warpM, warpN);
    const int wn = warp >> 2;
    const int g = lane >> 2, tig = lane & 3;

    float acc[2][8][4];
#pragma unroll
    for (int i = 0; i < 2; i++)
#pragma unroll
        for (int j = 0; j < 8; j++)
#pragma unroll
            for (int e = 0; e < 4; e++) acc[i][j][e] = 0.f;

    auto load_stage = [&](int st, int m) {
        const __half* a  = q + m * KC;
        const __half* dd = d + m * KC;
        const uint32_t smA = ring + (uint32_t)st * HSTG;
        const uint32_t smB = ring + MS_BOFF + (uint32_t)st * HSTG;
#pragma unroll
        for (int i = 0; i < 2; i++) {
            int idx = tid + i * 256;         // [0,512)
            int r = idx >> 2, c8 = (idx & 3) * 8;
            uint32_t off = (uint32_t)(r * LDH + c8) * 2;
            cp16(smA + off, a + (size_t)r * DDIM + c8);
            cp16(smB + off, dd + (size_t)r * DDIM + c8);
        }
    };

    load_stage(0, 0); CP_COMMIT();
    load_stage(1, 1); CP_COMMIT();

    const int NC = DDIM / KC;   // 4
    int st = 0, stn = 2;
    for (int k = 0; k < NC; k++) {
        CP_WAIT(1);
        __syncthreads();
        const int m = k + 2;
        if (m < NC) { load_stage(stn, m); CP_COMMIT(); }
        consume_stage16(ring + (uint32_t)st * HSTG,
                        ring + MS_BOFF + (uint32_t)st * HSTG,
                        aOff, bOff, acc);
        st = (st + 1 == NSTAGE) ? 0 : st + 1;
        stn = (stn + 1 == NSTAGE) ? 0 : stn + 1;
    }
    __syncthreads();

    // ---- row max over this 128-doc chunk ----
    float* mxb = (float*)(smem + RING_OFF + MS_RED);   // [2][128]
#pragma unroll
    for (int i = 0; i < 2; i++) {
        float ml = acc[i][0][0], mh = acc[i][0][2];
#pragma unroll
        for (int j = 0; j < 8; j++) {
            ml = fmaxf(ml, fmaxf(acc[i][j][0], acc[i][j][1]));
            mh = fmaxf(mh, fmaxf(acc[i][j][2], acc[i][j][3]));
        }
        ml = fmaxf(ml, __shfl_xor_sync(0xffffffffu, ml, 1));
        ml = fmaxf(ml, __shfl_xor_sync(0xffffffffu, ml, 2));
        mh = fmaxf(mh, __shfl_xor_sync(0xffffffffu, mh, 1));
        mh = fmaxf(mh, __shfl_xor_sync(0xffffffffu, mh, 2));
        if (tig == 0) {
            mxb[wn * 128 + warpM + i * 16 + g]     = ml;
            mxb[wn * 128 + warpM + i * 16 + 8 + g] = mh;
        }
    }
    __syncthreads();
    if (tid < 128)
        g_pmax[((size_t)b * NJCHUNK + jc) * SQ + tid] =
            fmaxf(mxb[tid], mxb[128 + tid]);
}

// ---------------------------------------------------------------------------
// Kernel 3: finalize. out[b] = sum_i max_jc pmax[b, jc, i]
// ---------------------------------------------------------------------------
__global__ __launch_bounds__(128) void finalize_kernel(float* __restrict__ out)
{
    const int b = blockIdx.x;
    const int i = threadIdx.x;
    float m = g_pmax[((size_t)b * NJCHUNK + 0) * SQ + i];
#pragma unroll
    for (int jc = 1; jc < NJCHUNK; jc++)
        m = fmaxf(m, g_pmax[((size_t)b * NJCHUNK + jc) * SQ + i]);
#pragma unroll
    for (int o = 16; o > 0; o >>= 1)
        m += __shfl_xor_sync(0xffffffffu, m, o, 32);
    __shared__ float s[4];
    if ((i & 31) == 0) s[i >> 5] = m;
    __syncthreads();
    if (i == 0) out[b] = s[0] + s[1] + s[2] + s[3];
}

// ---------------------------------------------------------------------------
extern "C" void kernel_launch(void* const* d_in, const int* in_sizes, int n_in,
                              void* d_out, int out_size)
{
    const float* qh = (const float*)d_in[0];   // [64,128,768]
    const int*   qm = (const int*)  d_in[1];   // [64,128]
    const float* dh = (const float*)d_in[2];   // [64,1024,768]
    const int*   dm = (const int*)  d_in[3];   // [64,1024]
    const float* W  = (const float*)d_in[4];   // [128,768]
    float* out = (float*)d_out;                // [64]

    cudaFuncSetAttribute(proj_tc,   cudaFuncAttributeMaxDynamicSharedMemorySize, PROJ_SMEM);
    cudaFuncSetAttribute(maxsim_tc, cudaFuncAttributeMaxDynamicSharedMemorySize, MS_SMEM);

    cvt_w<<<(DDIM * HDIM / 4) / 256, 256>>>(W);
    proj_tc<<<NBLK_Q + NBLK_D, 320, PROJ_SMEM>>>(qh, qm, dh, dm);
    maxsim_tc<<<dim3(BATCH, NJCHUNK), 256, MS_SMEM>>>();
    finalize_kernel<<<BATCH, 128>>>(out);
}